// round 8
// baseline (speedup 1.0000x reference)
#include <cuda_runtime.h>
#include <cstdint>

// Problem shape (fixed by reference)
#define BB 4
#define HH 16
#define SS 2048
#define DD 64
#define TQ 16            // queries per CTA
#define KC 128           // key chunk staged in smem
#define NCHUNK (SS/KC)   // 16
#define NT 256
#define SCALE 0.125f     // 1/sqrt(64)

// smem strides chosen for conflict-free MMA fragment loads
#define SSTR 2052        // scores row stride (2052 % 32 == 4 -> A-frag loads conflict-free)
#define KSTR 136         // KsT row stride  (136 % 32 == 8  -> B-frag loads conflict-free)
#define VSTR 132         // VsT row stride  (132 % 32 == 4  -> B-frag loads conflict-free)
#define KPLANE (DD*KSTR) // 8704 floats per K plane (hi or lo)
#define VPLANE (DD*VSTR) // 8448 floats per V plane

#define OUT_ELEMS (BB*HH*SS*DD)   // attention output; weights follow

// smem: scores[16][2052] + K/V hi+lo planes + Qs[16][64] + part[16][8] + invs[16]
#define SMEM_FLOATS (TQ*SSTR + 2*KPLANE + TQ*DD + 16*8 + 16)
#define SMEM_BYTES  (SMEM_FLOATS * 4)

__device__ __forceinline__ float tf32r(float x) {
    uint32_t u;
    asm("cvt.rna.tf32.f32 %0, %1;" : "=r"(u) : "f"(x));
    return __uint_as_float(u);
}

// D += A(16x8, tf32) * B(8x8, tf32), fp32 accumulate
#define MMA8(d, a0, a1, a2, a3, b0, b1)                                        \
    asm volatile(                                                              \
        "mma.sync.aligned.m16n8k8.row.col.f32.tf32.tf32.f32 "                  \
        "{%0,%1,%2,%3}, {%4,%5,%6,%7}, {%8,%9}, {%0,%1,%2,%3};"                \
        : "+f"(d[0]), "+f"(d[1]), "+f"(d[2]), "+f"(d[3])                       \
        : "r"(__float_as_uint(a0)), "r"(__float_as_uint(a1)),                  \
          "r"(__float_as_uint(a2)), "r"(__float_as_uint(a3)),                  \
          "r"(__float_as_uint(b0)), "r"(__float_as_uint(b1)))

__global__ __launch_bounds__(NT, 1)
void sdpa_tc2(const float* __restrict__ Q, const float* __restrict__ K,
              const float* __restrict__ V, const int* __restrict__ mask,
              float* __restrict__ out, float* __restrict__ wts) {
    extern __shared__ float smem[];
    float* scores = smem;                   // TQ * SSTR  (holds unnormalized e)
    float* KVbuf  = smem + TQ * SSTR;       // hi plane; lo plane follows
    float* Qs     = KVbuf + 2 * KPLANE;     // TQ * DD
    float* part   = Qs + TQ * DD;           // [16][8] per-warp row partial sums
    float* invs   = part + 16 * 8;          // [16] 1/rowsum

    const int h  = blockIdx.x;
    const int q0 = blockIdx.y * TQ;
    const int b  = blockIdx.z;

    const int tid = threadIdx.x;
    const int w   = tid >> 5;     // warp 0..7
    const int l   = tid & 31;
    const int g   = l >> 2;       // groupID 0..7
    const int tg  = l & 3;        // threadID-in-group 0..3

    const size_t bh = (size_t)(b * HH + h);
    const float4* Q4 = (const float4*)(Q + bh * SS * DD + (size_t)q0 * DD);
    const float4* K4 = (const float4*)(K + bh * SS * DD);
    const float4* V4 = (const float4*)(V + bh * SS * DD);
    const int*    Mb = mask + (size_t)b * SS * SS + (size_t)q0 * SS;
    float* Ob = out + bh * SS * DD + (size_t)q0 * DD;
    float* Wb = wts + bh * SS * SS + (size_t)q0 * SS;

    // Q tile to smem (256 float4 == NT threads)
    ((float4*)Qs)[tid] = Q4[tid];

    // Prefetch K chunk 0: thread owns d-cols {4w..4w+3, 4w+32..35}, keys 32i+l
    float4 pre[8];
#pragma unroll
    for (int p = 0; p < 2; p++)
#pragma unroll
        for (int i = 0; i < 4; i++)
            pre[p * 4 + i] = K4[(size_t)(32 * i + l) * (DD / 4) + w + 8 * p];

    __syncthreads();

    // Q fragments with SCALE folded in (hi/lo tf32 split), kept for all of phase 1.
    float qh[8][4], ql[8][4];
#pragma unroll
    for (int dk = 0; dk < 8; dk++) {
        float v0 = Qs[g * DD + 8 * dk + tg] * SCALE;
        float v1 = Qs[(g + 8) * DD + 8 * dk + tg] * SCALE;
        float v2 = Qs[g * DD + 8 * dk + tg + 4] * SCALE;
        float v3 = Qs[(g + 8) * DD + 8 * dk + tg + 4] * SCALE;
        qh[dk][0] = tf32r(v0); ql[dk][0] = tf32r(v0 - qh[dk][0]);
        qh[dk][1] = tf32r(v1); ql[dk][1] = tf32r(v1 - qh[dk][1]);
        qh[dk][2] = tf32r(v2); ql[dk][2] = tf32r(v2 - qh[dk][2]);
        qh[dk][3] = tf32r(v3); ql[dk][3] = tf32r(v3 - qh[dk][3]);
    }

    float s0 = 0.f, s1 = 0.f;   // running row sums for rows g, g+8

    // ===== Phase 1: e = exp(mask ? QK^T*SCALE : -inf), row sums in regs =====
    {
        float* KH = KVbuf;
        float* KL = KVbuf + KPLANE;
        for (int c = 0; c < NCHUNK; c++) {
            __syncthreads();   // protect KVbuf from previous chunk's readers
            // Stage prefetched K chunk, transposed + hi/lo split (conflict-free).
#pragma unroll
            for (int p = 0; p < 2; p++) {
                const int d0 = 4 * w + 32 * p;
#pragma unroll
                for (int i = 0; i < 4; i++) {
                    const int k = 32 * i + l;
                    float4 v = pre[p * 4 + i];
                    float x, hi;
                    x = v.x; hi = tf32r(x); KH[(d0 + 0) * KSTR + k] = hi; KL[(d0 + 0) * KSTR + k] = tf32r(x - hi);
                    x = v.y; hi = tf32r(x); KH[(d0 + 1) * KSTR + k] = hi; KL[(d0 + 1) * KSTR + k] = tf32r(x - hi);
                    x = v.z; hi = tf32r(x); KH[(d0 + 2) * KSTR + k] = hi; KL[(d0 + 2) * KSTR + k] = tf32r(x - hi);
                    x = v.w; hi = tf32r(x); KH[(d0 + 3) * KSTR + k] = hi; KL[(d0 + 3) * KSTR + k] = tf32r(x - hi);
                }
            }
            __syncthreads();
            // Prefetch next K chunk (or first V chunk after the last K chunk).
            if (c + 1 < NCHUNK) {
#pragma unroll
                for (int p = 0; p < 2; p++)
#pragma unroll
                    for (int i = 0; i < 4; i++)
                        pre[p * 4 + i] =
                            K4[(size_t)((c + 1) * KC + 32 * i + l) * (DD / 4) + w + 8 * p];
            } else {
#pragma unroll
                for (int p = 0; p < 2; p++)
#pragma unroll
                    for (int i = 0; i < 4; i++)
                        pre[p * 4 + i] = V4[(size_t)(32 * i + l) * (DD / 4) + w + 8 * p];
            }

            // Prefetch mask for this chunk's epilogue (in flight during MMAs).
            const int cbase = c * KC;
            int2 mreg[2][2];
#pragma unroll
            for (int jn = 0; jn < 2; jn++) {
                const int colj = cbase + (2 * w + jn) * 8 + 2 * tg;
                mreg[jn][0] = *(const int2*)&Mb[(size_t)g * SS + colj];
                mreg[jn][1] = *(const int2*)&Mb[(size_t)(g + 8) * SS + colj];
            }

            // MMAs: 2 n-tiles (16 keys) per warp, all 16 query rows, 3xTF32.
            float acc[2][4] = {{0.f, 0.f, 0.f, 0.f}, {0.f, 0.f, 0.f, 0.f}};
#pragma unroll
            for (int dk = 0; dk < 8; dk++) {
#pragma unroll
                for (int jn = 0; jn < 2; jn++) {
                    const int nc = (2 * w + jn) * 8;
                    const float* ph = &KH[(8 * dk + tg) * KSTR + nc + g];
                    const float* pl = &KL[(8 * dk + tg) * KSTR + nc + g];
                    float bh0 = ph[0], bh1 = ph[4 * KSTR];
                    float bl0 = pl[0], bl1 = pl[4 * KSTR];
                    MMA8(acc[jn], qh[dk][0], qh[dk][1], qh[dk][2], qh[dk][3], bh0, bh1);
                    MMA8(acc[jn], qh[dk][0], qh[dk][1], qh[dk][2], qh[dk][3], bl0, bl1);
                    MMA8(acc[jn], ql[dk][0], ql[dk][1], ql[dk][2], ql[dk][3], bh0, bh1);
                }
            }

            // Epilogue: mask -> exp -> store e -> accumulate row sums.
#pragma unroll
            for (int jn = 0; jn < 2; jn++) {
                const int colj = cbase + (2 * w + jn) * 8 + 2 * tg;
                float e0 = mreg[jn][0].x ? __expf(acc[jn][0]) : 0.f;
                float e1 = mreg[jn][0].y ? __expf(acc[jn][1]) : 0.f;
                float e2 = mreg[jn][1].x ? __expf(acc[jn][2]) : 0.f;
                float e3 = mreg[jn][1].y ? __expf(acc[jn][3]) : 0.f;
                *(float2*)&scores[g * SSTR + colj]       = make_float2(e0, e1);
                *(float2*)&scores[(g + 8) * SSTR + colj] = make_float2(e2, e3);
                s0 += e0 + e1;
                s1 += e2 + e3;
            }
        }
    }

    // ===== Row-sum reduction -> invs[16] =====
    s0 += __shfl_xor_sync(0xffffffffu, s0, 1);
    s0 += __shfl_xor_sync(0xffffffffu, s0, 2);
    s1 += __shfl_xor_sync(0xffffffffu, s1, 1);
    s1 += __shfl_xor_sync(0xffffffffu, s1, 2);
    if (tg == 0) {
        part[g * 8 + w]       = s0;
        part[(g + 8) * 8 + w] = s1;
    }
    __syncthreads();
    if (tid < 16) {
        float t = 0.f;
#pragma unroll
        for (int j = 0; j < 8; j++) t += part[tid * 8 + j];
        invs[tid] = 1.0f / t;
    }
    __syncthreads();

    const float invA  = invs[g];
    const float invB  = invs[g + 8];
    const float invW0 = invs[2 * w];
    const float invW1 = invs[2 * w + 1];

    // ===== Phase 3: out = (e*inv) @ V ; weights streamed per chunk =========
    {
        float* VH = KVbuf;
        float* VL = KVbuf + VPLANE;
        const int n0 = 8 * w;   // each warp owns 8 d-columns
        float oacc[2][4] = {{0.f, 0.f, 0.f, 0.f}, {0.f, 0.f, 0.f, 0.f}};

        for (int c = 0; c < NCHUNK; c++) {
            __syncthreads();
            // Stage V chunk transposed + split (conflict-free)
#pragma unroll
            for (int p = 0; p < 2; p++) {
                const int d0 = 4 * w + 32 * p;
#pragma unroll
                for (int i = 0; i < 4; i++) {
                    const int k = 32 * i + l;
                    float4 v = pre[p * 4 + i];
                    float x, hi;
                    x = v.x; hi = tf32r(x); VH[(d0 + 0) * VSTR + k] = hi; VL[(d0 + 0) * VSTR + k] = tf32r(x - hi);
                    x = v.y; hi = tf32r(x); VH[(d0 + 1) * VSTR + k] = hi; VL[(d0 + 1) * VSTR + k] = tf32r(x - hi);
                    x = v.z; hi = tf32r(x); VH[(d0 + 2) * VSTR + k] = hi; VL[(d0 + 2) * VSTR + k] = tf32r(x - hi);
                    x = v.w; hi = tf32r(x); VH[(d0 + 3) * VSTR + k] = hi; VL[(d0 + 3) * VSTR + k] = tf32r(x - hi);
                }
            }
            __syncthreads();
            if (c + 1 < NCHUNK) {
#pragma unroll
                for (int p = 0; p < 2; p++)
#pragma unroll
                    for (int i = 0; i < 4; i++)
                        pre[p * 4 + i] =
                            V4[(size_t)((c + 1) * KC + 32 * i + l) * (DD / 4) + w + 8 * p];
            }

            const int cbase = c * KC;

            // Fused weights write: warp w owns rows 2w, 2w+1; this chunk's cols.
            {
                const int r0 = 2 * w, r1 = 2 * w + 1;
                float4 v0 = *(const float4*)&scores[r0 * SSTR + cbase + 4 * l];
                float4 v1 = *(const float4*)&scores[r1 * SSTR + cbase + 4 * l];
                v0.x *= invW0; v0.y *= invW0; v0.z *= invW0; v0.w *= invW0;
                v1.x *= invW1; v1.y *= invW1; v1.z *= invW1; v1.w *= invW1;
                *(float4*)&Wb[(size_t)r0 * SS + cbase + 4 * l] = v0;
                *(float4*)&Wb[(size_t)r1 * SS + cbase + 4 * l] = v1;
            }

#pragma unroll
            for (int kt = 0; kt < 16; kt += 2) {
#pragma unroll
                for (int u = 0; u < 2; u++) {
                    const int k0  = (kt + u) * 8;     // key offset within chunk
                    const int kgl = cbase + k0;       // scores col
                    // A fragment = normalized P, built on the fly
                    float a0 = scores[g * SSTR + kgl + tg] * invA;
                    float a1 = scores[(g + 8) * SSTR + kgl + tg] * invB;
                    float a2 = scores[g * SSTR + kgl + tg + 4] * invA;
                    float a3 = scores[(g + 8) * SSTR + kgl + tg + 4] * invB;
                    float h0 = tf32r(a0), h1 = tf32r(a1), h2 = tf32r(a2), h3 = tf32r(a3);
                    float l0 = tf32r(a0 - h0), l1 = tf32r(a1 - h1);
                    float l2 = tf32r(a2 - h2), l3 = tf32r(a3 - h3);
                    const float* ph = &VH[(n0 + g) * VSTR + k0 + tg];
                    const float* pl = &VL[(n0 + g) * VSTR + k0 + tg];
                    float bh0 = ph[0], bh1 = ph[4];
                    float bl0 = pl[0], bl1 = pl[4];
                    MMA8(oacc[u], h0, h1, h2, h3, bh0, bh1);
                    MMA8(oacc[u], h0, h1, h2, h3, bl0, bl1);
                    MMA8(oacc[u], l0, l1, l2, l3, bh0, bh1);
                }
            }
        }

        const int col = n0 + 2 * tg;
        *(float2*)&Ob[(size_t)g * DD + col] =
            make_float2(oacc[0][0] + oacc[1][0], oacc[0][1] + oacc[1][1]);
        *(float2*)&Ob[(size_t)(g + 8) * DD + col] =
            make_float2(oacc[0][2] + oacc[1][2], oacc[0][3] + oacc[1][3]);
    }
}

extern "C" void kernel_launch(void* const* d_in, const int* in_sizes, int n_in,
                              void* d_out, int out_size) {
    (void)in_sizes; (void)n_in; (void)out_size;
    const float* Q    = (const float*)d_in[0];
    const float* K    = (const float*)d_in[1];
    const float* V    = (const float*)d_in[2];
    const int*   mask = (const int*)d_in[3];
    float* out = (float*)d_out;
    float* wts = out + OUT_ELEMS;

    static int smem_set = 0;
    if (!smem_set) {
        cudaFuncSetAttribute(sdpa_tc2,
                             cudaFuncAttributeMaxDynamicSharedMemorySize,
                             SMEM_BYTES);
        smem_set = 1;
    }

    dim3 grid(HH, SS / TQ, BB);  // h fastest -> mask tile reused across heads in L2
    sdpa_tc2<<<grid, NT, SMEM_BYTES>>>(Q, K, V, mask, out, wts);
}